// round 2
// baseline (speedup 1.0000x reference)
#include <cuda_runtime.h>
#include <math.h>

// NTM shapes
#define Bb 256
#define Tt 128
#define Ii 512
#define Hh 512
#define Nn 1024
#define Mm 512
#define Oo 512
#define NBLK 148
#define NTHR 256
#define BH (Bb * Hh)
#define BM (Bb * Mm)

// ---------------- persistent state / scratch (device globals) ---------------
__device__ float g_mem[Nn * Mm];
__device__ float g_wr[Bb * Nn];
__device__ float g_ww[Bb * Nn];
__device__ float g_h[Bb * Hh];
__device__ float g_ea[Bb * 2 * Mm];
__device__ float g_rpart[4 * Bb * Mm];
__device__ float g_hpart[4 * Bb * Hh];
__device__ float g_pw[Bb * (Mm + 6)];
__device__ float g_pr[Bb * (Mm + 6)];
__device__ float g_scw[Bb * 8];
__device__ float g_scr[Bb * 8];
__device__ float g_simw[Bb * Nn];
__device__ float g_simr[Bb * Nn];
__device__ float g_invmem[Nn];
__device__ unsigned g_bar_count;
__device__ unsigned g_bar_gen;

// ---------------- grid barrier (all NBLK blocks resident) -------------------
static __device__ __forceinline__ void gridBarrier() {
    __syncthreads();
    __threadfence();
    if (threadIdx.x == 0) {
        unsigned gen = *(volatile unsigned*)&g_bar_gen;
        unsigned prev = atomicAdd(&g_bar_count, 1u);
        if (prev == NBLK - 1) {
            g_bar_count = 0;
            __threadfence();
            *(volatile unsigned*)&g_bar_gen = gen + 1;
        } else {
            while (*(volatile unsigned*)&g_bar_gen == gen) { __nanosleep(64); }
        }
    }
    __syncthreads();
}

// ---------------- math helpers ----------------------------------------------
static __device__ __forceinline__ float sigm(float x) { return 1.f / (1.f + expf(-x)); }
static __device__ __forceinline__ float softplus_(float x) {
    return fmaxf(x, 0.f) + log1pf(expf(-fabsf(x)));
}
static __device__ __forceinline__ float warpReduceSum(float v) {
    #pragma unroll
    for (int o = 16; o > 0; o >>= 1) v += __shfl_xor_sync(0xffffffffu, v, o);
    return v;
}
static __device__ __forceinline__ float warpReduceMax(float v) {
    #pragma unroll
    for (int o = 16; o > 0; o >>= 1) v = fmaxf(v, __shfl_xor_sync(0xffffffffu, v, o));
    return v;
}
static __device__ __forceinline__ float blockReduceSum256(float v) {
    __shared__ float sh[8];
    int lane = threadIdx.x & 31, wid = threadIdx.x >> 5;
    v = warpReduceSum(v);
    if (lane == 0) sh[wid] = v;
    __syncthreads();
    if (wid == 0) {
        float t = (lane < 8) ? sh[lane] : 0.f;
        t = warpReduceSum(t);
        if (lane == 0) sh[0] = t;
    }
    __syncthreads();
    float r = sh[0];
    __syncthreads();
    return r;
}
static __device__ __forceinline__ float blockReduceMax256(float v) {
    __shared__ float sh[8];
    int lane = threadIdx.x & 31, wid = threadIdx.x >> 5;
    v = warpReduceMax(v);
    if (lane == 0) sh[wid] = v;
    __syncthreads();
    if (wid == 0) {
        float t = (lane < 8) ? sh[lane] : -3.4e38f;
        t = warpReduceMax(t);
        if (lane == 0) sh[0] = t;
    }
    __syncthreads();
    float r = sh[0];
    __syncthreads();
    return r;
}

// ---------------- 64x64 NN GEMM tile: C = act(A@W + bias) -------------------
// As padded to stride 68: conflict-light stores, aligned float4 reads.
// act: 0 none, 2 sigmoid, 3 tanh col<512, 4 sigmoid col<512 / tanh col>=512
static __device__ __forceinline__ void gemm64_nn(
    const float* __restrict__ A, int lda,
    const float* __restrict__ W, int ldw,
    const float* __restrict__ bias,
    float* __restrict__ C, int ldc,
    int bm, int bn, int Nc, int K, int act, float* shb)
{
    float (*As)[68] = (float(*)[68])shb;
    float (*Ws)[64] = (float(*)[64])(shb + 16 * 68);
    const int tid = threadIdx.x, tx = tid & 15, ty = tid >> 4;
    float acc[4][4] = {};
    for (int k0 = 0; k0 < K; k0 += 16) {
        #pragma unroll
        for (int i = 0; i < 4; i++) {
            int idx = tid + i * 256;
            int m = idx >> 4, kk = idx & 15;
            As[kk][m] = A[(bm + m) * lda + (k0 + kk)];
            int kk2 = idx >> 6, n = idx & 63;
            int col = bn + n;
            Ws[kk2][n] = (col < Nc) ? W[(k0 + kk2) * ldw + col] : 0.f;
        }
        __syncthreads();
        #pragma unroll
        for (int kk = 0; kk < 16; kk++) {
            float4 a4 = *(const float4*)&As[kk][ty * 4];
            float4 w4 = *(const float4*)&Ws[kk][tx * 4];
            float av[4] = {a4.x, a4.y, a4.z, a4.w};
            float wv[4] = {w4.x, w4.y, w4.z, w4.w};
            #pragma unroll
            for (int i = 0; i < 4; i++)
                #pragma unroll
                for (int j = 0; j < 4; j++)
                    acc[i][j] = fmaf(av[i], wv[j], acc[i][j]);
        }
        __syncthreads();
    }
    #pragma unroll
    for (int i = 0; i < 4; i++) {
        int row = bm + ty * 4 + i;
        #pragma unroll
        for (int j = 0; j < 4; j++) {
            int col = bn + tx * 4 + j;
            if (col >= Nc) continue;
            float v = acc[i][j];
            if (bias) v += bias[col];
            if (act == 2) v = sigm(v);
            else if (act == 3) { if (col < 512) v = tanhf(v); }
            else if (act == 4) { v = (col < 512) ? sigm(v) : tanhf(v); }
            C[row * ldc + col] = v;
        }
    }
}

// ---------------- 64x64 NT GEMM tile: C[b,n] = sum_k A[b,k]*Bm[n,k] ---------
static __device__ __forceinline__ void gemm64_nt(
    const float* __restrict__ A, int lda,
    const float* __restrict__ Bm, int ldb,
    float* __restrict__ C, int ldc,
    int bm, int bn, int K, float* shb)
{
    float (*As)[68] = (float(*)[68])shb;
    float (*Bs)[68] = (float(*)[68])(shb + 16 * 68);
    const int tid = threadIdx.x, tx = tid & 15, ty = tid >> 4;
    float acc[4][4] = {};
    for (int k0 = 0; k0 < K; k0 += 16) {
        #pragma unroll
        for (int i = 0; i < 4; i++) {
            int idx = tid + i * 256;
            int m = idx >> 4, kk = idx & 15;
            As[kk][m] = A[(bm + m) * lda + (k0 + kk)];
            Bs[kk][m] = Bm[(bn + m) * ldb + (k0 + kk)];
        }
        __syncthreads();
        #pragma unroll
        for (int kk = 0; kk < 16; kk++) {
            float4 a4 = *(const float4*)&As[kk][ty * 4];
            float4 w4 = *(const float4*)&Bs[kk][tx * 4];
            float av[4] = {a4.x, a4.y, a4.z, a4.w};
            float wv[4] = {w4.x, w4.y, w4.z, w4.w};
            #pragma unroll
            for (int i = 0; i < 4; i++)
                #pragma unroll
                for (int j = 0; j < 4; j++)
                    acc[i][j] = fmaf(av[i], wv[j], acc[i][j]);
        }
        __syncthreads();
    }
    #pragma unroll
    for (int i = 0; i < 4; i++) {
        int row = bm + ty * 4 + i;
        #pragma unroll
        for (int j = 0; j < 4; j++)
            C[row * ldc + (bn + tx * 4 + j)] = acc[i][j];
    }
}

// ---------------- mem update tile: mem = mem*(1 - ww^T e/B) + ww^T a/B ------
static __device__ __forceinline__ void memupd_tile(int tn, int tm, float* shb)
{
    float (*Wws)[64] = (float(*)[64])shb;
    float (*Es)[64]  = (float(*)[64])(shb + 1024);
    float (*Aas)[64] = (float(*)[64])(shb + 2048);
    const int bnrow = tn * 64, bmcol = tm * 64;
    const int tid = threadIdx.x, tx = tid & 15, ty = tid >> 4;
    float acce[4][4] = {};
    float acca[4][4] = {};
    for (int b0 = 0; b0 < Bb; b0 += 16) {
        #pragma unroll
        for (int i = 0; i < 4; i++) {
            int idx = tid + i * 256;
            int kk = idx >> 6, c = idx & 63;
            Wws[kk][c] = g_ww[(b0 + kk) * Nn + (bnrow + c)];
            Es[kk][c]  = g_ea[(b0 + kk) * (2 * Mm) + (bmcol + c)];
            Aas[kk][c] = g_ea[(b0 + kk) * (2 * Mm) + Mm + (bmcol + c)];
        }
        __syncthreads();
        #pragma unroll
        for (int kk = 0; kk < 16; kk++) {
            float wv[4];
            #pragma unroll
            for (int i = 0; i < 4; i++) wv[i] = Wws[kk][ty * 4 + i];
            float4 e4 = *(const float4*)&Es[kk][tx * 4];
            float4 a4 = *(const float4*)&Aas[kk][tx * 4];
            float ev[4] = {e4.x, e4.y, e4.z, e4.w};
            float av[4] = {a4.x, a4.y, a4.z, a4.w};
            #pragma unroll
            for (int i = 0; i < 4; i++)
                #pragma unroll
                for (int j = 0; j < 4; j++) {
                    acce[i][j] = fmaf(wv[i], ev[j], acce[i][j]);
                    acca[i][j] = fmaf(wv[i], av[j], acca[i][j]);
                }
        }
        __syncthreads();
    }
    const float invB = 1.f / (float)Bb;
    #pragma unroll
    for (int i = 0; i < 4; i++) {
        int n = bnrow + ty * 4 + i;
        #pragma unroll
        for (int j = 0; j < 4; j++) {
            int m = bmcol + tx * 4 + j;
            float old = g_mem[n * Mm + m];
            g_mem[n * Mm + m] = old * (1.f - acce[i][j] * invB) + acca[i][j] * invB;
        }
    }
}

// ---------------- controller split-K tile -----------------------------------
// chunk c: 0,1 -> x halves; 2,3 -> r (= sum of 4 rpart) halves. K=256 each.
static __device__ __forceinline__ void gemmD_tile(
    int c, int bm, int bn, const float* __restrict__ xb,
    const float* __restrict__ Wx, const float* __restrict__ Wr, float* shb)
{
    float (*As)[68] = (float(*)[68])shb;
    float (*Ws)[64] = (float(*)[64])(shb + 16 * 68);
    const int tid = threadIdx.x, tx = tid & 15, ty = tid >> 4;
    const float* W = (c < 2) ? (Wx + c * 256 * Hh) : (Wr + (c - 2) * 256 * Hh);
    float acc[4][4] = {};
    for (int k0 = 0; k0 < 256; k0 += 16) {
        #pragma unroll
        for (int i = 0; i < 4; i++) {
            int idx = tid + i * 256;
            int m = idx >> 4, kk = idx & 15;
            if (c < 2) {
                As[kk][m] = xb[(bm + m) * (Tt * Ii) + c * 256 + k0 + kk];
            } else {
                int off = (bm + m) * Mm + (c - 2) * 256 + k0 + kk;
                As[kk][m] = g_rpart[off] + g_rpart[off + BM]
                          + g_rpart[off + 2 * BM] + g_rpart[off + 3 * BM];
            }
            int kk2 = idx >> 6, n = idx & 63;
            Ws[kk2][n] = W[(k0 + kk2) * Hh + (bn + n)];
        }
        __syncthreads();
        #pragma unroll
        for (int kk = 0; kk < 16; kk++) {
            float4 a4 = *(const float4*)&As[kk][ty * 4];
            float4 w4 = *(const float4*)&Ws[kk][tx * 4];
            float av[4] = {a4.x, a4.y, a4.z, a4.w};
            float wv[4] = {w4.x, w4.y, w4.z, w4.w};
            #pragma unroll
            for (int i = 0; i < 4; i++)
                #pragma unroll
                for (int j = 0; j < 4; j++)
                    acc[i][j] = fmaf(av[i], wv[j], acc[i][j]);
        }
        __syncthreads();
    }
    float* C = g_hpart + c * BH;
    #pragma unroll
    for (int i = 0; i < 4; i++) {
        int row = bm + ty * 4 + i;
        #pragma unroll
        for (int j = 0; j < 4; j++)
            C[row * Hh + (bn + tx * 4 + j)] = acc[i][j];
    }
}

// ---------------- small row-wise items ---------------------------------------
static __device__ __noinline__ void invnorm_item(int item)
{
    int w = threadIdx.x >> 5, lane = threadIdx.x & 31;
    for (int rr = w; rr < 128; rr += 8) {
        int n = item * 128 + rr;
        float s = 0.f;
        for (int c = lane; c < Mm; c += 32) {
            float v = g_mem[n * Mm + c];
            s += v * v;
        }
        s = warpReduceSum(s);
        if (lane == 0) g_invmem[n] = 1.f / (sqrtf(s) + 1e-8f);
    }
}

static __device__ __noinline__ void scalars_item(int i)
{
    int head = i >> 3, rb = i & 7;
    const float* p = head ? g_pr : g_pw;
    float* sc = head ? g_scr : g_scw;
    int w = threadIdx.x >> 5, lane = threadIdx.x & 31;
    for (int rr = w; rr < 32; rr += 8) {
        int b = rb * 32 + rr;
        const float* row = p + b * (Mm + 6);
        float s = 0.f;
        for (int c = lane; c < Mm; c += 32) {
            float v = row[c];
            s += v * v;
        }
        s = warpReduceSum(s);
        if (lane == 0) {
            sc[b * 8 + 0] = softplus_(row[Mm + 0]);
            sc[b * 8 + 1] = sigm(row[Mm + 1]);
            float s0 = row[Mm + 2], s1 = row[Mm + 3], s2 = row[Mm + 4];
            float mx = fmaxf(s0, fmaxf(s1, s2));
            float e0 = expf(s0 - mx), e1 = expf(s1 - mx), e2 = expf(s2 - mx);
            float inv = 1.f / (e0 + e1 + e2);
            sc[b * 8 + 2] = e0 * inv;
            sc[b * 8 + 3] = e1 * inv;
            sc[b * 8 + 4] = e2 * inv;
            sc[b * 8 + 5] = 1.f + softplus_(row[Mm + 5]);
            sc[b * 8 + 6] = 1.f / (sqrtf(s) + 1e-8f);
        }
    }
}

// -------- fused address tail: softmax -> interpolate -> shift -> sharpen -----
static __device__ __noinline__ void tail_item(int it, float* shb)
{
    float* wg = shb;                  // 1024 floats
    int b = it & 255, head = it >> 8;
    const float* sim = head ? g_simr : g_simw;
    float* wv = head ? g_wr : g_ww;
    const float* sc = head ? g_scr : g_scw;
    int tid = threadIdx.x;
    float beta = sc[b * 8 + 0], g = sc[b * 8 + 1];
    float s0 = sc[b * 8 + 2], s1 = sc[b * 8 + 3], s2 = sc[b * 8 + 4];
    float gamma = sc[b * 8 + 5], invk = sc[b * 8 + 6];
    float scale = beta * invk;

    float v[4];
    float mx = -3.4e38f;
    #pragma unroll
    for (int i = 0; i < 4; i++) {
        int n = tid + i * 256;
        float t = sim[b * Nn + n] * scale * g_invmem[n];
        v[i] = t;
        mx = fmaxf(mx, t);
    }
    mx = blockReduceMax256(mx);
    float s = 0.f;
    #pragma unroll
    for (int i = 0; i < 4; i++) { v[i] = expf(v[i] - mx); s += v[i]; }
    s = blockReduceSum256(s);
    float invs = 1.f / s;
    #pragma unroll
    for (int i = 0; i < 4; i++) {
        int n = tid + i * 256;
        wg[n] = g * (v[i] * invs) + (1.f - g) * wv[b * Nn + n];
    }
    __syncthreads();
    float wp[4];
    float local = 0.f;
    #pragma unroll
    for (int i = 0; i < 4; i++) {
        int n = tid + i * 256;
        float wt = s0 * wg[(n + 1) & (Nn - 1)] + s1 * wg[n] + s2 * wg[(n - 1) & (Nn - 1)];
        float pv = powf(wt, gamma);
        wp[i] = pv;
        local += pv;
    }
    local = blockReduceSum256(local);
    float invt = 1.f / (local + 1e-8f);
    #pragma unroll
    for (int i = 0; i < 4; i++) {
        int n = tid + i * 256;
        wv[b * Nn + n] = wp[i] * invt;
    }
    __syncthreads();
}

// ---------------- the persistent kernel --------------------------------------
__global__ void __launch_bounds__(NTHR, 1) ntm_persistent(
    const float* __restrict__ x,
    const float* __restrict__ mem0, const float* __restrict__ wr0,
    const float* __restrict__ ww0,  const float* __restrict__ h0,
    const float* __restrict__ Wx,   const float* __restrict__ Wr,
    const float* __restrict__ bh,
    const float* __restrict__ Whr,  const float* __restrict__ bhr,
    const float* __restrict__ Whw,  const float* __restrict__ bhw,
    const float* __restrict__ Wea,  const float* __restrict__ bea,
    const float* __restrict__ Wo,   const float* __restrict__ bo,
    float* __restrict__ out)
{
    __shared__ __align__(16) float shbuf[3072];
    const int tid = threadIdx.x;
    const int gtid = blockIdx.x * NTHR + tid;
    const int gstride = NBLK * NTHR;

    // P0: init carried state
    for (int i = gtid; i < Nn * Mm; i += gstride) g_mem[i] = mem0[i];
    for (int i = gtid; i < Bb * Nn; i += gstride) { g_wr[i] = wr0[i]; g_ww[i] = ww0[i]; }
    for (int i = gtid; i < Bb * Hh; i += gstride) g_h[i] = h0[i];
    gridBarrier();

    // P1: ea from h0
    for (int it = blockIdx.x; it < 64; it += NBLK) {
        int tm = it >> 4, tn = it & 15;
        gemm64_nn(g_h, Hh, Wea, 2 * Mm, bea, g_ea, 2 * Mm,
                  tm * 64, tn * 64, 2 * Mm, Hh, 4, shbuf);
    }
    gridBarrier();

    for (int t = 0; t < Tt; t++) {
        // B: memory write (128 tiles)
        for (int it = blockIdx.x; it < 128; it += NBLK)
            memupd_tile(it >> 3, it & 7, shbuf);
        gridBarrier();

        // C: r split-K (128) + invnorm (8)
        for (int it = blockIdx.x; it < 136; it += NBLK) {
            if (it < 128) {
                int c = it >> 5, rest = it & 31, tm = rest >> 3, tn = rest & 7;
                gemm64_nn(g_wr + c * 256, Nn, g_mem + c * 256 * Mm, Mm, nullptr,
                          g_rpart + c * BM, Mm, tm * 64, tn * 64, Mm, 256, 0, shbuf);
            } else invnorm_item(it - 128);
        }
        gridBarrier();

        // D: controller split-K (128)
        for (int it = blockIdx.x; it < 128; it += NBLK) {
            int c = it >> 5, rest = it & 31, tm = rest >> 3, tn = rest & 7;
            gemmD_tile(c, tm * 64, tn * 64, x + (size_t)t * Ii, Wx, Wr, shbuf);
        }
        gridBarrier();

        // D2: h = tanh(sum hpart + bh)
        for (int i = gtid; i < BH; i += gstride)
            g_h[i] = tanhf(g_hpart[i] + g_hpart[i + BH] + g_hpart[i + 2 * BH]
                           + g_hpart[i + 3 * BH] + bh[i & 511]);
        gridBarrier();

        // E': pw(36) pr(36) out(32) ea-next(64) = 168
        for (int it = blockIdx.x; it < 168; it += NBLK) {
            if (it < 36) {
                int tm = it / 9, tn = it % 9;
                gemm64_nn(g_h, Hh, Whw, Mm + 6, bhw, g_pw, Mm + 6,
                          tm * 64, tn * 64, Mm + 6, Hh, 3, shbuf);
            } else if (it < 72) {
                int i2 = it - 36, tm = i2 / 9, tn = i2 % 9;
                gemm64_nn(g_h, Hh, Whr, Mm + 6, bhr, g_pr, Mm + 6,
                          tm * 64, tn * 64, Mm + 6, Hh, 3, shbuf);
            } else if (it < 104) {
                int i2 = it - 72, tm = i2 >> 3, tn = i2 & 7;
                gemm64_nn(g_h, Hh, Wo, Oo, bo, out + (size_t)t * Oo, Tt * Oo,
                          tm * 64, tn * 64, Oo, Hh, 2, shbuf);
            } else {
                int i2 = it - 104, tm = i2 >> 4, tn = i2 & 15;
                gemm64_nn(g_h, Hh, Wea, 2 * Mm, bea, g_ea, 2 * Mm,
                          tm * 64, tn * 64, 2 * Mm, Hh, 4, shbuf);
            }
        }
        gridBarrier();

        // F: simw(64) simr(64) + head scalars(16)
        for (int it = blockIdx.x; it < 144; it += NBLK) {
            if (it < 64) {
                int tm = it >> 4, tn = it & 15;
                gemm64_nt(g_pw, Mm + 6, g_mem, Mm, g_simw, Nn,
                          tm * 64, tn * 64, Mm, shbuf);
            } else if (it < 128) {
                int i2 = it - 64, tm = i2 >> 4, tn = i2 & 15;
                gemm64_nt(g_pr, Mm + 6, g_mem, Mm, g_simr, Nn,
                          tm * 64, tn * 64, Mm, shbuf);
            } else scalars_item(it - 128);
        }
        gridBarrier();

        // G: address tails (512 rows)
        for (int it = blockIdx.x; it < 512; it += NBLK)
            tail_item(it, shbuf);
        gridBarrier();
    }
}

// ---------------- host --------------------------------------------------------
extern "C" void kernel_launch(void* const* d_in, const int* in_sizes, int n_in,
                              void* d_out, int out_size)
{
    const float* x    = (const float*)d_in[0];
    const float* mem0 = (const float*)d_in[1];
    const float* wr0  = (const float*)d_in[2];
    const float* ww0  = (const float*)d_in[3];
    const float* h0   = (const float*)d_in[4];
    const float* Wx   = (const float*)d_in[5];
    const float* Wr   = (const float*)d_in[6];
    const float* bh   = (const float*)d_in[7];
    const float* Whr  = (const float*)d_in[8];
    const float* bhr  = (const float*)d_in[9];
    const float* Whw  = (const float*)d_in[10];
    const float* bhw  = (const float*)d_in[11];
    const float* Wea  = (const float*)d_in[12];
    const float* bea  = (const float*)d_in[13];
    const float* Wo   = (const float*)d_in[14];
    const float* bo   = (const float*)d_in[15];
    float* out = (float*)d_out;

    ntm_persistent<<<NBLK, NTHR>>>(x, mem0, wr0, ww0, h0, Wx, Wr, bh,
                                   Whr, bhr, Whw, bhw, Wea, bea, Wo, bo, out);
}

// round 3
// speedup vs baseline: 1.2371x; 1.2371x over previous
#include <cuda_runtime.h>
#include <math.h>

// NTM shapes
#define Bb 256
#define Tt 128
#define Ii 512
#define Hh 512
#define Nn 1024
#define Mm 512
#define Oo 512
#define NBLK 148
#define NTHR 256
#define BH (Bb * Hh)
#define BM (Bb * Mm)

// ---------------- persistent state / scratch (device globals) ---------------
__device__ float g_mem[Nn * Mm];
__device__ float g_wr[Bb * Nn];
__device__ float g_ww[Bb * Nn];
__device__ float g_h[Bb * Hh];
__device__ float g_ea[Bb * 2 * Mm];
__device__ float g_rpart[4 * Bb * Mm];
__device__ float g_hpart[4 * Bb * Hh];
__device__ float g_pw[Bb * (Mm + 6)];
__device__ float g_pr[Bb * (Mm + 6)];
__device__ float g_scw[Bb * 8];
__device__ float g_scr[Bb * 8];
__device__ float g_simw[Bb * Nn];
__device__ float g_simr[Bb * Nn];
__device__ float g_invmem[Nn];
__device__ unsigned g_bar_count;
__device__ unsigned g_bar_gen;

// ---------------- grid barrier ----------------------------------------------
static __device__ __forceinline__ void gridBarrier() {
    __syncthreads();
    __threadfence();
    if (threadIdx.x == 0) {
        unsigned gen = *(volatile unsigned*)&g_bar_gen;
        unsigned prev = atomicAdd(&g_bar_count, 1u);
        if (prev == NBLK - 1) {
            g_bar_count = 0;
            __threadfence();
            *(volatile unsigned*)&g_bar_gen = gen + 1;
        } else {
            while (*(volatile unsigned*)&g_bar_gen == gen) { __nanosleep(64); }
        }
    }
    __syncthreads();
}

// ---------------- math helpers ----------------------------------------------
static __device__ __forceinline__ float sigm(float x) { return 1.f / (1.f + __expf(-x)); }
static __device__ __forceinline__ float tanh_f(float x) {
    float t = __expf(-2.f * fabsf(x));          // in (0,1], no overflow
    float r = (1.f - t) / (1.f + t);
    return copysignf(r, x);
}
static __device__ __forceinline__ float softplus_(float x) {
    return fmaxf(x, 0.f) + log1pf(__expf(-fabsf(x)));
}
static __device__ __forceinline__ float warpReduceSum(float v) {
    #pragma unroll
    for (int o = 16; o > 0; o >>= 1) v += __shfl_xor_sync(0xffffffffu, v, o);
    return v;
}
static __device__ __forceinline__ float warpReduceMax(float v) {
    #pragma unroll
    for (int o = 16; o > 0; o >>= 1) v = fmaxf(v, __shfl_xor_sync(0xffffffffu, v, o));
    return v;
}
static __device__ __forceinline__ float blockReduceSum256(float v) {
    __shared__ float sh[8];
    int lane = threadIdx.x & 31, wid = threadIdx.x >> 5;
    v = warpReduceSum(v);
    if (lane == 0) sh[wid] = v;
    __syncthreads();
    if (wid == 0) {
        float t = (lane < 8) ? sh[lane] : 0.f;
        t = warpReduceSum(t);
        if (lane == 0) sh[0] = t;
    }
    __syncthreads();
    float r = sh[0];
    __syncthreads();
    return r;
}
static __device__ __forceinline__ float blockReduceMax256(float v) {
    __shared__ float sh[8];
    int lane = threadIdx.x & 31, wid = threadIdx.x >> 5;
    v = warpReduceMax(v);
    if (lane == 0) sh[wid] = v;
    __syncthreads();
    if (wid == 0) {
        float t = (lane < 8) ? sh[lane] : -3.4e38f;
        t = warpReduceMax(t);
        if (lane == 0) sh[0] = t;
    }
    __syncthreads();
    float r = sh[0];
    __syncthreads();
    return r;
}

#define FMA16(acc, a4, w4)                                            \
    {                                                                 \
        float av_[4] = {a4.x, a4.y, a4.z, a4.w};                      \
        float wv_[4] = {w4.x, w4.y, w4.z, w4.w};                      \
        _Pragma("unroll")                                             \
        for (int i_ = 0; i_ < 4; i_++)                                \
            _Pragma("unroll")                                         \
            for (int j_ = 0; j_ < 4; j_++)                            \
                acc[i_][j_] = fmaf(av_[i_], wv_[j_], acc[i_][j_]);    \
    }

// ---------------- 64x64 NN GEMM tile, double-buffered -----------------------
// C = act(A@W + bias).  act: 0 none, 2 sigmoid, 3 tanh col<512, 4 sig|tanh.
static __device__ __forceinline__ void gemm64_nn(
    const float* __restrict__ A, int lda,
    const float* __restrict__ W, int ldw,
    const float* __restrict__ bias,
    float* __restrict__ C, int ldc,
    int bm, int bn, int Nc, int K, int act, float* shb)
{
    float (*As)[16][68] = (float(*)[16][68])shb;
    float (*Ws)[16][64] = (float(*)[16][64])(shb + 2 * 16 * 68);
    const int tid = threadIdx.x, tx = tid & 15, ty = tid >> 4;
    const int am = tid >> 4, ak = tid & 15;
    const int wk = tid >> 6, wn = tid & 63;
    const float* Aptr = A + (size_t)(bm + am) * lda + ak;
    const float* Wptr = W + (size_t)wk * ldw + bn + wn;
    const bool wok = (bn + wn) < Nc;

    float acc[4][4] = {};
    float ra[4], rw[4];
    #pragma unroll
    for (int i = 0; i < 4; i++) {
        ra[i] = Aptr[i * 16 * lda];
        rw[i] = wok ? Wptr[(size_t)(i * 4) * ldw] : 0.f;
    }
    #pragma unroll
    for (int i = 0; i < 4; i++) {
        As[0][ak][am + 16 * i] = ra[i];
        Ws[0][wk + 4 * i][wn] = rw[i];
    }
    __syncthreads();
    int buf = 0;
    for (int k0 = 0; k0 < K; k0 += 16) {
        if (k0 + 16 < K) {
            const float* Ap = Aptr + (k0 + 16);
            const float* Wp = Wptr + (size_t)(k0 + 16) * ldw;
            #pragma unroll
            for (int i = 0; i < 4; i++) {
                ra[i] = Ap[i * 16 * lda];
                rw[i] = wok ? Wp[(size_t)(i * 4) * ldw] : 0.f;
            }
        }
        #pragma unroll
        for (int kk = 0; kk < 16; kk++) {
            float4 a4 = *(const float4*)&As[buf][kk][ty * 4];
            float4 w4 = *(const float4*)&Ws[buf][kk][tx * 4];
            FMA16(acc, a4, w4);
        }
        if (k0 + 16 < K) {
            __syncthreads();
            #pragma unroll
            for (int i = 0; i < 4; i++) {
                As[buf ^ 1][ak][am + 16 * i] = ra[i];
                Ws[buf ^ 1][wk + 4 * i][wn] = rw[i];
            }
            __syncthreads();
            buf ^= 1;
        }
    }
    __syncthreads();
    #pragma unroll
    for (int i = 0; i < 4; i++) {
        int row = bm + ty * 4 + i;
        #pragma unroll
        for (int j = 0; j < 4; j++) {
            int col = bn + tx * 4 + j;
            if (col >= Nc) continue;
            float v = acc[i][j];
            if (bias) v += bias[col];
            if (act == 2) v = sigm(v);
            else if (act == 3) { if (col < 512) v = tanh_f(v); }
            else if (act == 4) { v = (col < 512) ? sigm(v) : tanh_f(v); }
            C[(size_t)row * ldc + col] = v;
        }
    }
}

// ---------------- 64x64 NT GEMM tile, double-buffered ------------------------
static __device__ __forceinline__ void gemm64_nt(
    const float* __restrict__ A, int lda,
    const float* __restrict__ Bm, int ldb,
    float* __restrict__ C, int ldc,
    int bm, int bn, int K, float* shb)
{
    float (*As)[16][68] = (float(*)[16][68])shb;
    float (*Bs)[16][68] = (float(*)[16][68])(shb + 2 * 16 * 68);
    const int tid = threadIdx.x, tx = tid & 15, ty = tid >> 4;
    const int am = tid >> 4, ak = tid & 15;
    const float* Aptr = A + (size_t)(bm + am) * lda + ak;
    const float* Bptr = Bm + (size_t)(bn + am) * ldb + ak;

    float acc[4][4] = {};
    float ra[4], rb[4];
    #pragma unroll
    for (int i = 0; i < 4; i++) {
        ra[i] = Aptr[i * 16 * lda];
        rb[i] = Bptr[i * 16 * ldb];
    }
    #pragma unroll
    for (int i = 0; i < 4; i++) {
        As[0][ak][am + 16 * i] = ra[i];
        Bs[0][ak][am + 16 * i] = rb[i];
    }
    __syncthreads();
    int buf = 0;
    for (int k0 = 0; k0 < K; k0 += 16) {
        if (k0 + 16 < K) {
            const float* Ap = Aptr + (k0 + 16);
            const float* Bp = Bptr + (k0 + 16);
            #pragma unroll
            for (int i = 0; i < 4; i++) {
                ra[i] = Ap[i * 16 * lda];
                rb[i] = Bp[i * 16 * ldb];
            }
        }
        #pragma unroll
        for (int kk = 0; kk < 16; kk++) {
            float4 a4 = *(const float4*)&As[buf][kk][ty * 4];
            float4 w4 = *(const float4*)&Bs[buf][kk][tx * 4];
            FMA16(acc, a4, w4);
        }
        if (k0 + 16 < K) {
            __syncthreads();
            #pragma unroll
            for (int i = 0; i < 4; i++) {
                As[buf ^ 1][ak][am + 16 * i] = ra[i];
                Bs[buf ^ 1][ak][am + 16 * i] = rb[i];
            }
            __syncthreads();
            buf ^= 1;
        }
    }
    __syncthreads();
    #pragma unroll
    for (int i = 0; i < 4; i++) {
        int row = bm + ty * 4 + i;
        #pragma unroll
        for (int j = 0; j < 4; j++)
            C[(size_t)row * ldc + (bn + tx * 4 + j)] = acc[i][j];
    }
}

// ---------------- mem update tile, double-buffered ---------------------------
static __device__ __forceinline__ void memupd_tile(int tn, int tm, float* shb)
{
    float (*Wws)[16][68] = (float(*)[16][68])shb;
    float (*Es)[16][68]  = (float(*)[16][68])(shb + 2 * 16 * 68);
    float (*Aas)[16][68] = (float(*)[16][68])(shb + 4 * 16 * 68);
    const int bnrow = tn * 64, bmcol = tm * 64;
    const int tid = threadIdx.x, tx = tid & 15, ty = tid >> 4;
    const int lk = tid >> 6, lc = tid & 63;
    const float* wp = g_ww + (size_t)lk * Nn + bnrow + lc;
    const float* ep = g_ea + (size_t)lk * (2 * Mm) + bmcol + lc;
    const float* ap = ep + Mm;

    float acce[4][4] = {};
    float acca[4][4] = {};
    float rw[4], re[4], rr[4];
    #pragma unroll
    for (int i = 0; i < 4; i++) {
        rw[i] = wp[(size_t)(4 * i) * Nn];
        re[i] = ep[(size_t)(4 * i) * (2 * Mm)];
        rr[i] = ap[(size_t)(4 * i) * (2 * Mm)];
    }
    #pragma unroll
    for (int i = 0; i < 4; i++) {
        Wws[0][lk + 4 * i][lc] = rw[i];
        Es[0][lk + 4 * i][lc] = re[i];
        Aas[0][lk + 4 * i][lc] = rr[i];
    }
    __syncthreads();
    int buf = 0;
    for (int b0 = 0; b0 < Bb; b0 += 16) {
        if (b0 + 16 < Bb) {
            const float* wp2 = wp + (size_t)(b0 + 16) * Nn;
            const float* ep2 = ep + (size_t)(b0 + 16) * (2 * Mm);
            const float* ap2 = ap + (size_t)(b0 + 16) * (2 * Mm);
            #pragma unroll
            for (int i = 0; i < 4; i++) {
                rw[i] = wp2[(size_t)(4 * i) * Nn];
                re[i] = ep2[(size_t)(4 * i) * (2 * Mm)];
                rr[i] = ap2[(size_t)(4 * i) * (2 * Mm)];
            }
        }
        #pragma unroll
        for (int kk = 0; kk < 16; kk++) {
            float4 w4 = *(const float4*)&Wws[buf][kk][ty * 4];
            float4 e4 = *(const float4*)&Es[buf][kk][tx * 4];
            float4 a4 = *(const float4*)&Aas[buf][kk][tx * 4];
            float wv[4] = {w4.x, w4.y, w4.z, w4.w};
            float ev[4] = {e4.x, e4.y, e4.z, e4.w};
            float av[4] = {a4.x, a4.y, a4.z, a4.w};
            #pragma unroll
            for (int i = 0; i < 4; i++)
                #pragma unroll
                for (int j = 0; j < 4; j++) {
                    acce[i][j] = fmaf(wv[i], ev[j], acce[i][j]);
                    acca[i][j] = fmaf(wv[i], av[j], acca[i][j]);
                }
        }
        if (b0 + 16 < Bb) {
            __syncthreads();
            #pragma unroll
            for (int i = 0; i < 4; i++) {
                Wws[buf ^ 1][lk + 4 * i][lc] = rw[i];
                Es[buf ^ 1][lk + 4 * i][lc] = re[i];
                Aas[buf ^ 1][lk + 4 * i][lc] = rr[i];
            }
            __syncthreads();
            buf ^= 1;
        }
    }
    __syncthreads();
    const float invB = 1.f / (float)Bb;
    #pragma unroll
    for (int i = 0; i < 4; i++) {
        int n = bnrow + ty * 4 + i;
        #pragma unroll
        for (int j = 0; j < 4; j++) {
            int m = bmcol + tx * 4 + j;
            float old = g_mem[(size_t)n * Mm + m];
            g_mem[(size_t)n * Mm + m] = old * (1.f - acce[i][j] * invB) + acca[i][j] * invB;
        }
    }
}

// ---------------- controller split-K tile, double-buffered -------------------
// chunk c: 0,1 -> x halves; 2,3 -> r (= sum of 4 rpart) halves. K=256 each.
static __device__ __forceinline__ void gemmD_tile(
    int c, int bm, int bn, const float* __restrict__ xb,
    const float* __restrict__ Wx, const float* __restrict__ Wr, float* shb)
{
    float (*As)[16][68] = (float(*)[16][68])shb;
    float (*Ws)[16][64] = (float(*)[16][64])(shb + 2 * 16 * 68);
    const int tid = threadIdx.x, tx = tid & 15, ty = tid >> 4;
    const int am = tid >> 4, ak = tid & 15;
    const int wk = tid >> 6, wn = tid & 63;
    const float* W = ((c < 2) ? (Wx + (size_t)c * 256 * Hh) : (Wr + (size_t)(c - 2) * 256 * Hh))
                     + (size_t)wk * Hh + bn + wn;
    const float* Ax = xb + (size_t)(bm + am) * (Tt * Ii) + c * 256 + ak;
    const float* Ar = g_rpart + (size_t)(bm + am) * Mm + (c - 2) * 256 + ak;

    float acc[4][4] = {};
    float ra[4], rw[4];
    #pragma unroll
    for (int i = 0; i < 4; i++) {
        if (c < 2) ra[i] = Ax[(size_t)(i * 16) * (Tt * Ii)];
        else {
            const float* p = Ar + (size_t)(i * 16) * Mm;
            ra[i] = p[0] + p[BM] + p[2 * BM] + p[3 * BM];
        }
        rw[i] = W[(size_t)(i * 4) * Hh];
    }
    #pragma unroll
    for (int i = 0; i < 4; i++) {
        As[0][ak][am + 16 * i] = ra[i];
        Ws[0][wk + 4 * i][wn] = rw[i];
    }
    __syncthreads();
    int buf = 0;
    for (int k0 = 0; k0 < 256; k0 += 16) {
        if (k0 + 16 < 256) {
            #pragma unroll
            for (int i = 0; i < 4; i++) {
                if (c < 2) ra[i] = Ax[(size_t)(i * 16) * (Tt * Ii) + k0 + 16];
                else {
                    const float* p = Ar + (size_t)(i * 16) * Mm + k0 + 16;
                    ra[i] = p[0] + p[BM] + p[2 * BM] + p[3 * BM];
                }
                rw[i] = W[(size_t)(k0 + 16 + i * 4) * Hh];
            }
        }
        #pragma unroll
        for (int kk = 0; kk < 16; kk++) {
            float4 a4 = *(const float4*)&As[buf][kk][ty * 4];
            float4 w4 = *(const float4*)&Ws[buf][kk][tx * 4];
            FMA16(acc, a4, w4);
        }
        if (k0 + 16 < 256) {
            __syncthreads();
            #pragma unroll
            for (int i = 0; i < 4; i++) {
                As[buf ^ 1][ak][am + 16 * i] = ra[i];
                Ws[buf ^ 1][wk + 4 * i][wn] = rw[i];
            }
            __syncthreads();
            buf ^= 1;
        }
    }
    __syncthreads();
    float* C = g_hpart + (size_t)c * BH;
    #pragma unroll
    for (int i = 0; i < 4; i++) {
        int row = bm + ty * 4 + i;
        #pragma unroll
        for (int j = 0; j < 4; j++)
            C[(size_t)row * Hh + (bn + tx * 4 + j)] = acc[i][j];
    }
}

// ---------------- small row-wise items ---------------------------------------
static __device__ __noinline__ void invnorm_item(int item)
{
    int w = threadIdx.x >> 5, lane = threadIdx.x & 31;
    for (int rr = w; rr < 128; rr += 8) {
        int n = item * 128 + rr;
        float s = 0.f;
        for (int c = lane; c < Mm; c += 32) {
            float v = g_mem[(size_t)n * Mm + c];
            s += v * v;
        }
        s = warpReduceSum(s);
        if (lane == 0) g_invmem[n] = 1.f / (sqrtf(s) + 1e-8f);
    }
}

static __device__ __noinline__ void scalars_item(int i)
{
    int head = i >> 3, rb = i & 7;
    const float* p = head ? g_pr : g_pw;
    float* sc = head ? g_scr : g_scw;
    int w = threadIdx.x >> 5, lane = threadIdx.x & 31;
    for (int rr = w; rr < 32; rr += 8) {
        int b = rb * 32 + rr;
        const float* row = p + (size_t)b * (Mm + 6);
        float s = 0.f;
        for (int c = lane; c < Mm; c += 32) {
            float v = row[c];
            s += v * v;
        }
        s = warpReduceSum(s);
        if (lane == 0) {
            sc[b * 8 + 0] = softplus_(row[Mm + 0]);
            sc[b * 8 + 1] = sigm(row[Mm + 1]);
            float s0 = row[Mm + 2], s1 = row[Mm + 3], s2 = row[Mm + 4];
            float mx = fmaxf(s0, fmaxf(s1, s2));
            float e0 = __expf(s0 - mx), e1 = __expf(s1 - mx), e2 = __expf(s2 - mx);
            float inv = 1.f / (e0 + e1 + e2);
            sc[b * 8 + 2] = e0 * inv;
            sc[b * 8 + 3] = e1 * inv;
            sc[b * 8 + 4] = e2 * inv;
            sc[b * 8 + 5] = 1.f + softplus_(row[Mm + 5]);
            sc[b * 8 + 6] = 1.f / (sqrtf(s) + 1e-8f);
        }
    }
}

// -------- fused address tail: softmax -> interpolate -> shift -> sharpen -----
static __device__ __noinline__ void tail_item(int it, float* shb)
{
    float* wg = shb;                  // 1024 floats
    int b = it & 255, head = it >> 8;
    const float* sim = head ? g_simr : g_simw;
    float* wv = head ? g_wr : g_ww;
    const float* sc = head ? g_scr : g_scw;
    int tid = threadIdx.x;
    float beta = sc[b * 8 + 0], g = sc[b * 8 + 1];
    float s0 = sc[b * 8 + 2], s1 = sc[b * 8 + 3], s2 = sc[b * 8 + 4];
    float gamma = sc[b * 8 + 5], invk = sc[b * 8 + 6];
    float scale = beta * invk;

    float v[4];
    float mx = -3.4e38f;
    #pragma unroll
    for (int i = 0; i < 4; i++) {
        int n = tid + i * 256;
        float t = sim[(size_t)b * Nn + n] * scale * g_invmem[n];
        v[i] = t;
        mx = fmaxf(mx, t);
    }
    mx = blockReduceMax256(mx);
    float s = 0.f;
    #pragma unroll
    for (int i = 0; i < 4; i++) { v[i] = __expf(v[i] - mx); s += v[i]; }
    s = blockReduceSum256(s);
    float invs = 1.f / s;
    #pragma unroll
    for (int i = 0; i < 4; i++) {
        int n = tid + i * 256;
        wg[n] = g * (v[i] * invs) + (1.f - g) * wv[(size_t)b * Nn + n];
    }
    __syncthreads();
    float wp[4];
    float local = 0.f;
    #pragma unroll
    for (int i = 0; i < 4; i++) {
        int n = tid + i * 256;
        float wt = s0 * wg[(n + 1) & (Nn - 1)] + s1 * wg[n] + s2 * wg[(n - 1) & (Nn - 1)];
        float pv = __powf(wt, gamma);
        wp[i] = pv;
        local += pv;
    }
    local = blockReduceSum256(local);
    float invt = 1.f / (local + 1e-8f);
    #pragma unroll
    for (int i = 0; i < 4; i++) {
        int n = tid + i * 256;
        wv[(size_t)b * Nn + n] = wp[i] * invt;
    }
    __syncthreads();
}

// ---------------- the persistent kernel --------------------------------------
__global__ void __launch_bounds__(NTHR, 1) ntm_persistent(
    const float* __restrict__ x,
    const float* __restrict__ mem0, const float* __restrict__ wr0,
    const float* __restrict__ ww0,  const float* __restrict__ h0,
    const float* __restrict__ Wx,   const float* __restrict__ Wr,
    const float* __restrict__ bh,
    const float* __restrict__ Whr,  const float* __restrict__ bhr,
    const float* __restrict__ Whw,  const float* __restrict__ bhw,
    const float* __restrict__ Wea,  const float* __restrict__ bea,
    const float* __restrict__ Wo,   const float* __restrict__ bo,
    float* __restrict__ out)
{
    __shared__ __align__(16) float shbuf[6 * 16 * 68];   // 26.1 KB
    const int tid = threadIdx.x;
    const int gtid = blockIdx.x * NTHR + tid;
    const int gstride = NBLK * NTHR;

    // P0: init carried state
    for (int i = gtid; i < Nn * Mm; i += gstride) g_mem[i] = mem0[i];
    for (int i = gtid; i < Bb * Nn; i += gstride) { g_wr[i] = wr0[i]; g_ww[i] = ww0[i]; }
    for (int i = gtid; i < Bb * Hh; i += gstride) g_h[i] = h0[i];
    gridBarrier();

    // P1: ea from h0
    for (int it = blockIdx.x; it < 64; it += NBLK) {
        int tm = it >> 4, tn = it & 15;
        gemm64_nn(g_h, Hh, Wea, 2 * Mm, bea, g_ea, 2 * Mm,
                  tm * 64, tn * 64, 2 * Mm, Hh, 4, shbuf);
    }
    gridBarrier();

    for (int t = 0; t < Tt; t++) {
        // B: memory write (128 tiles)
        for (int it = blockIdx.x; it < 128; it += NBLK)
            memupd_tile(it >> 3, it & 7, shbuf);
        gridBarrier();

        // C: r split-K (128) + invnorm (8)
        for (int it = blockIdx.x; it < 136; it += NBLK) {
            if (it < 128) {
                int c = it >> 5, rest = it & 31, tm = rest >> 3, tn = rest & 7;
                gemm64_nn(g_wr + c * 256, Nn, g_mem + (size_t)c * 256 * Mm, Mm, nullptr,
                          g_rpart + (size_t)c * BM, Mm, tm * 64, tn * 64, Mm, 256, 0, shbuf);
            } else invnorm_item(it - 128);
        }
        gridBarrier();

        // D: controller split-K (128)
        for (int it = blockIdx.x; it < 128; it += NBLK) {
            int c = it >> 5, rest = it & 31, tm = rest >> 3, tn = rest & 7;
            gemmD_tile(c, tm * 64, tn * 64, x + (size_t)t * Ii, Wx, Wr, shbuf);
        }
        gridBarrier();

        // D2: h = tanh(sum hpart + bh)
        for (int i = gtid; i < BH; i += gstride)
            g_h[i] = tanh_f(g_hpart[i] + g_hpart[i + BH] + g_hpart[i + 2 * BH]
                            + g_hpart[i + 3 * BH] + bh[i & 511]);
        gridBarrier();

        // E: pw(36) pr(36) out(32) ea-next(64) = 168
        for (int it = blockIdx.x; it < 168; it += NBLK) {
            if (it < 36) {
                int tm = it / 9, tn = it % 9;
                gemm64_nn(g_h, Hh, Whw, Mm + 6, bhw, g_pw, Mm + 6,
                          tm * 64, tn * 64, Mm + 6, Hh, 3, shbuf);
            } else if (it < 72) {
                int i2 = it - 36, tm = i2 / 9, tn = i2 % 9;
                gemm64_nn(g_h, Hh, Whr, Mm + 6, bhr, g_pr, Mm + 6,
                          tm * 64, tn * 64, Mm + 6, Hh, 3, shbuf);
            } else if (it < 104) {
                int i2 = it - 72, tm = i2 >> 3, tn = i2 & 7;
                gemm64_nn(g_h, Hh, Wo, Oo, bo, out + (size_t)t * Oo, Tt * Oo,
                          tm * 64, tn * 64, Oo, Hh, 2, shbuf);
            } else {
                int i2 = it - 104, tm = i2 >> 4, tn = i2 & 15;
                gemm64_nn(g_h, Hh, Wea, 2 * Mm, bea, g_ea, 2 * Mm,
                          tm * 64, tn * 64, 2 * Mm, Hh, 4, shbuf);
            }
        }
        gridBarrier();

        // F: simw(64) simr(64) + head scalars(16)
        for (int it = blockIdx.x; it < 144; it += NBLK) {
            if (it < 64) {
                int tm = it >> 4, tn = it & 15;
                gemm64_nt(g_pw, Mm + 6, g_mem, Mm, g_simw, Nn,
                          tm * 64, tn * 64, Mm, shbuf);
            } else if (it < 128) {
                int i2 = it - 64, tm = i2 >> 4, tn = i2 & 15;
                gemm64_nt(g_pr, Mm + 6, g_mem, Mm, g_simr, Nn,
                          tm * 64, tn * 64, Mm, shbuf);
            } else scalars_item(it - 128);
        }
        gridBarrier();

        // G: address tails (512 rows)
        for (int it = blockIdx.x; it < 512; it += NBLK)
            tail_item(it, shbuf);
        gridBarrier();
    }
}

// ---------------- host --------------------------------------------------------
extern "C" void kernel_launch(void* const* d_in, const int* in_sizes, int n_in,
                              void* d_out, int out_size)
{
    const float* x    = (const float*)d_in[0];
    const float* mem0 = (const float*)d_in[1];
    const float* wr0  = (const float*)d_in[2];
    const float* ww0  = (const float*)d_in[3];
    const float* h0   = (const float*)d_in[4];
    const float* Wx   = (const float*)d_in[5];
    const float* Wr   = (const float*)d_in[6];
    const float* bh   = (const float*)d_in[7];
    const float* Whr  = (const float*)d_in[8];
    const float* bhr  = (const float*)d_in[9];
    const float* Whw  = (const float*)d_in[10];
    const float* bhw  = (const float*)d_in[11];
    const float* Wea  = (const float*)d_in[12];
    const float* bea  = (const float*)d_in[13];
    const float* Wo   = (const float*)d_in[14];
    const float* bo   = (const float*)d_in[15];
    float* out = (float*)d_out;

    ntm_persistent<<<NBLK, NTHR>>>(x, mem0, wr0, ww0, h0, Wx, Wr, bh,
                                   Whr, bhr, Whw, bhw, Wea, bea, Wo, bo, out);
}